// round 15
// baseline (speedup 1.0000x reference)
#include <cuda_runtime.h>
#include <cuda_bf16.h>
#include <math.h>
#include <stdint.h>

// ---------------- problem constants ----------------
#define BB   2
#define LL   2048
#define DM   1024
#define DI   2048
#define DTR  64
#define DS   16
#define MTOK (BB * LL)   // 4096 tokens
#define XDBL_W 96
#define GCH  16          // scan chunks
#define CHLEN (LL / GCH) // 128
#define XKSPLIT 4

// ---------------- scratch ----------------
__device__ float    g_xdbl [(size_t)MTOK * XDBL_W];
__device__ float    g_delta[(size_t)MTOK * DI];
__device__ float    g_xpart[(size_t)XKSPLIT * MTOK * XDBL_W];
__device__ uint32_t g_xn16   [(size_t)MTOK * DM / 2];
__device__ uint32_t g_xz16   [(size_t)MTOK * 2 * DI / 2];   // u|z bf16 packed
__device__ uint32_t g_uconv16[(size_t)MTOK * DI / 2];
__device__ uint32_t g_dt16   [(size_t)MTOK * DTR / 2];
__device__ __nv_bfloat16 g_y16[(size_t)MTOK * DI];
__device__ uint32_t g_win16  [(size_t)2 * DI * DM / 2];
__device__ uint32_t g_wx16   [(size_t)XDBL_W * DI / 2];
__device__ uint32_t g_wdt16  [(size_t)DI * DTR / 2];
__device__ uint32_t g_wout16 [(size_t)DM * DI / 2];
// scan carries: [(b*DI+dd)*DS+n][GCH]
__device__ float g_Ac[(size_t)BB * DI * DS * GCH];
__device__ float g_Hc[(size_t)BB * DI * DS * GCH];
__device__ float g_Ci[(size_t)BB * DI * DS * GCH];

// ---------------- helpers ----------------
__device__ __forceinline__ float softplus_f(float v) {
    return (v > 20.f) ? v : log1pf(__expf(v));
}
__device__ __forceinline__ float silu_f(float v) {
    return v * (1.f / (1.f + __expf(-v)));
}
__device__ __forceinline__ uint32_t packbf(float lo, float hi) {
    __nv_bfloat162 h(__float2bfloat16_rn(lo), __float2bfloat16_rn(hi));
    return *reinterpret_cast<uint32_t*>(&h);
}
__device__ __forceinline__ float2 unpk(uint32_t v) {
    __nv_bfloat162 h = *reinterpret_cast<__nv_bfloat162*>(&v);
    return make_float2(__bfloat162float(h.x), __bfloat162float(h.y));
}
__device__ __forceinline__ void mma_bf16(float* c, const uint32_t* a, const uint32_t* b) {
    asm volatile("mma.sync.aligned.m16n8k16.row.col.f32.bf16.bf16.f32 "
                 "{%0,%1,%2,%3}, {%4,%5,%6,%7}, {%8,%9}, {%0,%1,%2,%3};"
                 : "+f"(c[0]), "+f"(c[1]), "+f"(c[2]), "+f"(c[3])
                 : "r"(a[0]), "r"(a[1]), "r"(a[2]), "r"(a[3]),
                   "r"(b[0]), "r"(b[1]));
}
__device__ __forceinline__ void cp16(void* dst, const void* src) {
    uint32_t d = (uint32_t)__cvta_generic_to_shared(dst);
    asm volatile("cp.async.cg.shared.global [%0], [%1], 16;" :: "r"(d), "l"(src));
}
__device__ __forceinline__ uint32_t smem_u32(const void* p) {
    uint32_t a;
    asm("{ .reg .u64 t; cvta.to.shared.u64 t, %1; cvt.u32.u64 %0, t; }"
        : "=r"(a) : "l"(p));
    return a;
}
__device__ __forceinline__ void ldm_x4(uint32_t* r, uint32_t addr) {
    asm volatile("ldmatrix.sync.aligned.m8n8.x4.shared.b16 {%0,%1,%2,%3}, [%4];"
        : "=r"(r[0]), "=r"(r[1]), "=r"(r[2]), "=r"(r[3]) : "r"(addr));
}

// ---------------- one fused weight conversion ----------------
#define CN1 (2 * DI * DM / 2)
#define CN2 (XDBL_W * DI / 2)
#define CN3 (DI * DTR / 2)
#define CN4 (DM * DI / 2)
__global__ void convert_all(const float* __restrict__ w1, const float* __restrict__ w2,
                            const float* __restrict__ w3, const float* __restrict__ w4,
                            uint32_t* __restrict__ d1, uint32_t* __restrict__ d2,
                            uint32_t* __restrict__ d3, uint32_t* __restrict__ d4) {
    int i = blockIdx.x * blockDim.x + threadIdx.x;
    const float2* s; uint32_t* d; int j;
    if (i < CN1)                      { s = (const float2*)w1; d = d1; j = i; }
    else if (i < CN1 + CN2)           { s = (const float2*)w2; d = d2; j = i - CN1; }
    else if (i < CN1 + CN2 + CN3)     { s = (const float2*)w3; d = d3; j = i - CN1 - CN2; }
    else if (i < CN1 + CN2 + CN3 + CN4){ s = (const float2*)w4; d = d4; j = i - CN1 - CN2 - CN3; }
    else return;
    float2 v = s[j];
    d[j] = packbf(v.x, v.y);
}

// ---------------- LayerNorm -> bf16 packed ----------------
__global__ void ln_kernel(const float* __restrict__ x,
                          const float* __restrict__ w,
                          const float* __restrict__ b,
                          uint32_t* __restrict__ out16) {
    const int row = blockIdx.x;
    const int tid = threadIdx.x;
    const float4* xr = (const float4*)(x + (size_t)row * DM);
    float4 v = xr[tid];

    float s  = v.x + v.y + v.z + v.w;
    float s2 = v.x * v.x + v.y * v.y + v.z * v.z + v.w * v.w;

    __shared__ float shs[8], shs2[8];
    #pragma unroll
    for (int o = 16; o > 0; o >>= 1) {
        s  += __shfl_down_sync(0xffffffffu, s,  o);
        s2 += __shfl_down_sync(0xffffffffu, s2, o);
    }
    if ((tid & 31) == 0) { shs[tid >> 5] = s; shs2[tid >> 5] = s2; }
    __syncthreads();
    float mu = 0.f, m2 = 0.f;
    #pragma unroll
    for (int i = 0; i < 8; i++) { mu += shs[i]; m2 += shs2[i]; }
    mu *= (1.f / DM);
    m2 *= (1.f / DM);
    float inv = rsqrtf(m2 - mu * mu + 1e-5f);

    float4 wv = ((const float4*)w)[tid];
    float4 bv = ((const float4*)b)[tid];
    uint2 p;
    p.x = packbf((v.x - mu) * inv * wv.x + bv.x, (v.y - mu) * inv * wv.y + bv.y);
    p.y = packbf((v.z - mu) * inv * wv.z + bv.z, (v.w - mu) * inv * wv.w + bv.w);
    ((uint2*)(out16 + (size_t)row * (DM / 2)))[tid] = p;
}

// ---------------- bf16 mma.sync GEMM (ldmatrix, split-K, 3-stage) -----------
// EPI: 0 plain fp32, 1 softplus(v+aux[n]) fp32, 2 v+aux[m*ldc+n],
//      4 bf16-only -> Cb
template<int BM, int BN, int WM, int WN, int EPI>
__global__ __launch_bounds__(WM * WN * 32)
void gemm_lm(const uint32_t* __restrict__ A, int ldaU,
             const uint32_t* __restrict__ W, int ldwU,
             float* __restrict__ C, int ldc, int K,
             const float* __restrict__ aux,
             uint32_t* __restrict__ Cb, int ldcbU,
             int kSliceU, size_t cSliceF) {
    constexpr int NTHR = WM * WN * 32;
    constexpr int BK2 = 16;
    constexpr int STR = 20;
    constexpr int S = 3;
    constexpr int WARP_M = BM / WM;
    constexpr int WARP_N = BN / WN;
    constexpr int MT = WARP_M / 16;
    constexpr int NT = WARP_N / 8;
    static_assert(NT % 2 == 0, "NT must be even for x4 B loads");

    __shared__ __align__(16) uint32_t As[S][BM][STR];
    __shared__ __align__(16) uint32_t Bs[S][BN][STR];

    const int kz = blockIdx.z;
    A += (size_t)kz * kSliceU;
    W += (size_t)kz * kSliceU;
    C += (size_t)kz * cSliceF;

    const int tid  = threadIdx.x;
    const int lane = tid & 31;
    const int warp = tid >> 5;
    const int gid  = lane >> 2;
    const int tig  = lane & 3;

    const int bm0 = blockIdx.y * BM;
    const int bn0 = blockIdx.x * BN;
    const int wm0 = (warp / WN) * WARP_M;
    const int wn0 = (warp % WN) * WARP_N;

    float acc[MT][NT][4];
    #pragma unroll
    for (int i = 0; i < MT; i++)
        #pragma unroll
        for (int j = 0; j < NT; j++)
            #pragma unroll
            for (int e = 0; e < 4; e++) acc[i][j][e] = 0.f;

    auto load_tile = [&](int buf, int kt) {
        const int k0 = kt * BK2;
        #pragma unroll
        for (int s = tid; s < BM * 4; s += NTHR) {
            int r = s >> 2, c = (s & 3) * 4;
            cp16(&As[buf][r][c], A + (size_t)(bm0 + r) * ldaU + k0 + c);
        }
        #pragma unroll
        for (int s = tid; s < BN * 4; s += NTHR) {
            int r = s >> 2, c = (s & 3) * 4;
            cp16(&Bs[buf][r][c], W + (size_t)(bn0 + r) * ldwU + k0 + c);
        }
        asm volatile("cp.async.commit_group;");
    };

    const int nkt = K / 32;
    load_tile(0, 0);
    if (nkt > 1) load_tile(1, 1);

    const uint32_t a_row = (uint32_t)(lane & 15);
    const uint32_t a_col = (uint32_t)((lane >> 4) << 2);
    const uint32_t b_row = (uint32_t)((lane & 7) + ((lane >> 4) << 3));
    const uint32_t b_col = (uint32_t)(((lane >> 3) & 1) << 2);

    for (int kt = 0; kt < nkt; kt++) {
        const int buf = kt % S;
        if (kt + 1 < nkt) asm volatile("cp.async.wait_group 1;");
        else              asm volatile("cp.async.wait_group 0;");
        __syncthreads();
        if (kt + 2 < nkt) load_tile((kt + 2) % S, kt + 2);

        const uint32_t abase = smem_u32(&As[buf][0][0]);
        const uint32_t bbase = smem_u32(&Bs[buf][0][0]);

        #pragma unroll
        for (int ks = 0; ks < 2; ks++) {
            uint32_t af[MT][4];
            uint32_t bf[NT][2];
            #pragma unroll
            for (int mt = 0; mt < MT; mt++) {
                uint32_t r = (uint32_t)(wm0 + mt * 16) + a_row;
                ldm_x4(af[mt], abase + (r * STR + ks * 8 + a_col) * 4);
            }
            #pragma unroll
            for (int ip = 0; ip < NT / 2; ip++) {
                uint32_t r = (uint32_t)(wn0 + ip * 16) + b_row;
                uint32_t q[4];
                ldm_x4(q, bbase + (r * STR + ks * 8 + b_col) * 4);
                bf[2 * ip][0]     = q[0]; bf[2 * ip][1]     = q[1];
                bf[2 * ip + 1][0] = q[2]; bf[2 * ip + 1][1] = q[3];
            }
            #pragma unroll
            for (int mt = 0; mt < MT; mt++)
                #pragma unroll
                for (int nt = 0; nt < NT; nt++)
                    mma_bf16(acc[mt][nt], af[mt], bf[nt]);
        }
    }

    #pragma unroll
    for (int mt = 0; mt < MT; mt++) {
        int r0 = bm0 + wm0 + mt * 16 + gid;
        int r1 = r0 + 8;
        #pragma unroll
        for (int nt = 0; nt < NT; nt++) {
            int cn = bn0 + wn0 + nt * 8 + 2 * tig;
            float v0 = acc[mt][nt][0], v1 = acc[mt][nt][1];
            float v2 = acc[mt][nt][2], v3 = acc[mt][nt][3];
            if (EPI == 4) {
                Cb[(size_t)r0 * ldcbU + cn / 2] = packbf(v0, v1);
                Cb[(size_t)r1 * ldcbU + cn / 2] = packbf(v2, v3);
                continue;
            }
            if (EPI == 1) {
                v0 = softplus_f(v0 + aux[cn]);   v1 = softplus_f(v1 + aux[cn + 1]);
                v2 = softplus_f(v2 + aux[cn]);   v3 = softplus_f(v3 + aux[cn + 1]);
            }
            if (EPI == 2) {
                v0 += aux[(size_t)r0 * ldc + cn];  v1 += aux[(size_t)r0 * ldc + cn + 1];
                v2 += aux[(size_t)r1 * ldc + cn];  v3 += aux[(size_t)r1 * ldc + cn + 1];
            }
            *(float2*)(C + (size_t)r0 * ldc + cn) = make_float2(v0, v1);
            *(float2*)(C + (size_t)r1 * ldc + cn) = make_float2(v2, v3);
        }
    }
}

// ---------------- x_proj split-K reduce: partials -> xdbl + dt16 ------------
__global__ void xproj_reduce(const float* __restrict__ parts,
                             float* __restrict__ xdbl,
                             uint32_t* __restrict__ dt16) {
    int idx = blockIdx.x * blockDim.x + threadIdx.x;     // float2 index
    if (idx >= MTOK * XDBL_W / 2) return;
    float2 s = make_float2(0.f, 0.f);
    #pragma unroll
    for (int z = 0; z < XKSPLIT; z++) {
        float2 v = ((const float2*)(parts + (size_t)z * MTOK * XDBL_W))[idx];
        s.x += v.x; s.y += v.y;
    }
    ((float2*)xdbl)[idx] = s;
    int col2 = idx % (XDBL_W / 2);
    if (col2 < DTR / 2) {
        int row = idx / (XDBL_W / 2);
        dt16[(size_t)row * (DTR / 2) + col2] = packbf(s.x, s.y);
    }
}

// ---------------- causal conv(4) + bias + SiLU (bf16, 4 channels/thread) ---
__global__ void conv_silu_kernel(const uint32_t* __restrict__ xz16,
                                 const float* __restrict__ cw,
                                 const float* __restrict__ cb,
                                 uint32_t* __restrict__ out16) {
    int idx = blockIdx.x * blockDim.x + threadIdx.x;   // quad index (4 chans)
    if (idx >= MTOK * DI / 4) return;
    int q  = idx % (DI / 4);
    int d  = q * 4;
    int t  = idx / (DI / 4);
    int l  = t % LL;

    const uint2* up = (const uint2*)(xz16 + (size_t)t * (2 * DI / 2)) + q;
    const ptrdiff_t rowstride = (2 * DI / 2) / 2;
    uint2 z2 = make_uint2(0u, 0u);
    uint2 q0 = up[0];
    uint2 q1 = (l >= 1) ? up[-rowstride * 1] : z2;
    uint2 q2 = (l >= 2) ? up[-rowstride * 2] : z2;
    uint2 q3 = (l >= 3) ? up[-rowstride * 3] : z2;

    float2 c0a = unpk(q0.x), c0b = unpk(q0.y);
    float2 c1a = unpk(q1.x), c1b = unpk(q1.y);
    float2 c2a = unpk(q2.x), c2b = unpk(q2.y);
    float2 c3a = unpk(q3.x), c3b = unpk(q3.y);

    float4 w0 = *(const float4*)(cw + (size_t)(d + 0) * 4);
    float4 w1 = *(const float4*)(cw + (size_t)(d + 1) * 4);
    float4 w2 = *(const float4*)(cw + (size_t)(d + 2) * 4);
    float4 w3 = *(const float4*)(cw + (size_t)(d + 3) * 4);
    float4 bb = *(const float4*)(cb + d);

    float r0 = silu_f(w0.w * c0a.x + w0.z * c1a.x + w0.y * c2a.x + w0.x * c3a.x + bb.x);
    float r1 = silu_f(w1.w * c0a.y + w1.z * c1a.y + w1.y * c2a.y + w1.x * c3a.y + bb.y);
    float r2 = silu_f(w2.w * c0b.x + w2.z * c1b.x + w2.y * c2b.x + w2.x * c3b.x + bb.z);
    float r3 = silu_f(w3.w * c0b.y + w3.z * c1b.y + w3.y * c2b.y + w3.x * c3b.y + bb.w);

    uint2 o;
    o.x = packbf(r0, r1);
    o.y = packbf(r2, r3);
    ((uint2*)out16)[idx] = o;
}

// ---------------- chunked selective scan (split kernels, U=8 unroll) --------
__global__ void scan_p1(const float* __restrict__ delta,
                        const uint32_t* __restrict__ u16,
                        const float* __restrict__ xdbl,
                        const float* __restrict__ A_log,
                        float* __restrict__ gAc, float* __restrict__ gHc) {
    int gt   = blockIdx.x * blockDim.x + threadIdx.x;
    int w    = gt >> 5;
    int lane = gt & 31;
    if (w >= BB * (DI / 2) * GCH) return;

    int pair = w & 1023;
    int b    = (w >> 10) & 1;
    int g    = w >> 11;
    int hi   = lane >> 4;
    int dd   = pair * 2 + hi;
    int n    = lane & 15;
    int t0   = g * CHLEN;

    float Ad = -expf(A_log[dd * DS + n]);
    float h = 0.f, ap = 1.f;

    const size_t base_d = (size_t)(b * LL + t0) * DI + dd;
    const size_t base_u = (size_t)(b * LL + t0) * (DI / 2) + pair;
    const size_t base_x = (size_t)(b * LL + t0) * XDBL_W;

    constexpr int U = 8;
    float de[U], Bn[U];
    uint32_t uup[U];
    #pragma unroll
    for (int j = 0; j < U; j++) {
        de[j]  = delta[base_d + (size_t)j * DI];
        uup[j] = u16 [base_u + (size_t)j * (DI / 2)];
        Bn[j]  = xdbl[base_x + (size_t)j * XDBL_W + DTR + n];
    }
    for (int t = 0; t < CHLEN; t += U) {
        float cde[U], cuu[U], cBn[U];
        #pragma unroll
        for (int j = 0; j < U; j++) {
            cde[j] = de[j]; cBn[j] = Bn[j];
            float2 uv = unpk(uup[j]);
            cuu[j] = hi ? uv.y : uv.x;
        }
        if (t + U < CHLEN) {
            const size_t od = base_d + (size_t)(t + U) * DI;
            const size_t ou = base_u + (size_t)(t + U) * (DI / 2);
            const size_t ox = base_x + (size_t)(t + U) * XDBL_W;
            #pragma unroll
            for (int j = 0; j < U; j++) {
                de[j]  = delta[od + (size_t)j * DI];
                uup[j] = u16 [ou + (size_t)j * (DI / 2)];
                Bn[j]  = xdbl[ox + (size_t)j * XDBL_W + DTR + n];
            }
        }
        #pragma unroll
        for (int j = 0; j < U; j++) {
            float dA = __expf(cde[j] * Ad);
            h = fmaf(dA, h, cde[j] * cuu[j] * cBn[j]);
            ap *= dA;
        }
    }
    size_t idx = ((size_t)(b * DI + dd) * DS + n) * GCH + g;
    gAc[idx] = ap;
    gHc[idx] = h;
}

__global__ void scan_p2(const float* __restrict__ gAc,
                        const float* __restrict__ gHc,
                        float* __restrict__ gCi) {
    int i = blockIdx.x * blockDim.x + threadIdx.x;
    if (i >= BB * DI * DS) return;
    size_t base = (size_t)i * GCH;
    float c = 0.f;
    #pragma unroll
    for (int g = 0; g < GCH; g++) {
        gCi[base + g] = c;
        c = fmaf(gAc[base + g], c, gHc[base + g]);
    }
}

__global__ void scan_p3(const float* __restrict__ delta,
                        const uint32_t* __restrict__ u16,
                        const float* __restrict__ xdbl,
                        const uint32_t* __restrict__ xz16,
                        const float* __restrict__ A_log,
                        const float* __restrict__ Dp,
                        const float* __restrict__ gCi,
                        __nv_bfloat16* __restrict__ y16) {
    int gt   = blockIdx.x * blockDim.x + threadIdx.x;
    int w    = gt >> 5;
    int lane = gt & 31;
    if (w >= BB * (DI / 2) * GCH) return;

    int pair = w & 1023;
    int b    = (w >> 10) & 1;
    int g    = w >> 11;
    int hi   = lane >> 4;
    int dd   = pair * 2 + hi;
    int n    = lane & 15;
    int t0   = g * CHLEN;

    float Ad = -expf(A_log[dd * DS + n]);
    float Dd = Dp[dd];
    float h  = gCi[((size_t)(b * DI + dd) * DS + n) * GCH + g];

    const size_t base_d = (size_t)(b * LL + t0) * DI + dd;
    const size_t base_u = (size_t)(b * LL + t0) * (DI / 2) + pair;
    const size_t base_x = (size_t)(b * LL + t0) * XDBL_W;
    const size_t base_z = (size_t)(b * LL + t0) * (2 * DI / 2) + DI / 2 + pair;

    constexpr int U = 8;
    float de[U], Bn[U], Cn[U];
    uint32_t uup[U], zzp[U];
    #pragma unroll
    for (int j = 0; j < U; j++) {
        de[j]  = delta[base_d + (size_t)j * DI];
        uup[j] = u16 [base_u + (size_t)j * (DI / 2)];
        Bn[j]  = xdbl[base_x + (size_t)j * XDBL_W + DTR + n];
        Cn[j]  = xdbl[base_x + (size_t)j * XDBL_W + DTR + DS + n];
        zzp[j] = xz16[base_z + (size_t)j * (2 * DI / 2)];
    }
    for (int t = 0; t < CHLEN; t += U) {
        float cde[U], cuu[U], cBn[U], cCn[U], czv[U];
        #pragma unroll
        for (int j = 0; j < U; j++) {
            float2 uv = unpk(uup[j]);
            float2 zv = unpk(zzp[j]);
            cde[j] = de[j];
            cuu[j] = hi ? uv.y : uv.x;
            czv[j] = hi ? zv.y : zv.x;
            cBn[j] = Bn[j];
            cCn[j] = Cn[j];
        }
        if (t + U < CHLEN) {
            const size_t od = base_d + (size_t)(t + U) * DI;
            const size_t ou = base_u + (size_t)(t + U) * (DI / 2);
            const size_t ox = base_x + (size_t)(t + U) * XDBL_W;
            const size_t oz = base_z + (size_t)(t + U) * (2 * DI / 2);
            #pragma unroll
            for (int j = 0; j < U; j++) {
                de[j]  = delta[od + (size_t)j * DI];
                uup[j] = u16 [ou + (size_t)j * (DI / 2)];
                Bn[j]  = xdbl[ox + (size_t)j * XDBL_W + DTR + n];
                Cn[j]  = xdbl[ox + (size_t)j * XDBL_W + DTR + DS + n];
                zzp[j] = xz16[oz + (size_t)j * (2 * DI / 2)];
            }
        }
        float yv[U];
        #pragma unroll
        for (int j = 0; j < U; j++) {
            float dA = __expf(cde[j] * Ad);
            h = fmaf(dA, h, cde[j] * cuu[j] * cBn[j]);
            yv[j] = h * cCn[j];
        }
        #pragma unroll
        for (int o = 8; o > 0; o >>= 1) {
            #pragma unroll
            for (int j = 0; j < U; j++)
                yv[j] += __shfl_xor_sync(0xffffffffu, yv[j], o);
        }
        if (n == 0) {
            #pragma unroll
            for (int j = 0; j < U; j++)
                y16[base_d + (size_t)(t + j) * DI] =
                    __float2bfloat16_rn((yv[j] + cuu[j] * Dd) * silu_f(czv[j]));
        }
    }
}

// ---------------- launch ----------------------------------------------------
extern "C" void kernel_launch(void* const* d_in, const int* in_sizes, int n_in,
                              void* d_out, int out_size) {
    const float* x         = (const float*)d_in[0];
    const float* ln_w      = (const float*)d_in[1];
    const float* ln_b      = (const float*)d_in[2];
    const float* in_proj_w = (const float*)d_in[3];
    const float* conv_w    = (const float*)d_in[4];
    const float* conv_b    = (const float*)d_in[5];
    const float* x_proj_w  = (const float*)d_in[6];
    const float* dt_proj_w = (const float*)d_in[7];
    const float* dt_proj_b = (const float*)d_in[8];
    const float* A_log     = (const float*)d_in[9];
    const float* Dp        = (const float*)d_in[10];
    const float* out_pw    = (const float*)d_in[11];
    float* out = (float*)d_out;

    float *xdbl, *delta, *xpart, *Ac, *Hc, *Ci;
    uint32_t *xn16, *xz16, *uconv16, *dt16, *win16, *wx16, *wdt16, *wout16;
    __nv_bfloat16* y16;
    cudaGetSymbolAddress((void**)&xdbl,    g_xdbl);
    cudaGetSymbolAddress((void**)&delta,   g_delta);
    cudaGetSymbolAddress((void**)&xpart,   g_xpart);
    cudaGetSymbolAddress((void**)&xn16,    g_xn16);
    cudaGetSymbolAddress((void**)&xz16,    g_xz16);
    cudaGetSymbolAddress((void**)&uconv16, g_uconv16);
    cudaGetSymbolAddress((void**)&dt16,    g_dt16);
    cudaGetSymbolAddress((void**)&y16,     g_y16);
    cudaGetSymbolAddress((void**)&win16,   g_win16);
    cudaGetSymbolAddress((void**)&wx16,    g_wx16);
    cudaGetSymbolAddress((void**)&wdt16,   g_wdt16);
    cudaGetSymbolAddress((void**)&wout16,  g_wout16);
    cudaGetSymbolAddress((void**)&Ac,      g_Ac);
    cudaGetSymbolAddress((void**)&Hc,      g_Hc);
    cudaGetSymbolAddress((void**)&Ci,      g_Ci);

    // 0. fused weight conversion
    {
        int tot = CN1 + CN2 + CN3 + CN4;
        convert_all<<<(tot + 255) / 256, 256>>>(
            in_proj_w, x_proj_w, dt_proj_w, out_pw, win16, wx16, wdt16, wout16);
    }

    // 1. LayerNorm -> xn16
    ln_kernel<<<MTOK, 256>>>(x, ln_w, ln_b, xn16);

    // 2. in_proj -> xz16 (bf16), 64x64 warp tile
    gemm_lm<128, 128, 2, 2, 4><<<dim3((2 * DI) / 128, MTOK / 128), 128>>>(
        xn16, DM / 2, win16, DM / 2, nullptr, 0, DM, nullptr,
        xz16, 2 * DI / 2, 0, 0);

    // 3. conv + SiLU -> uconv16 (4 channels/thread)
    conv_silu_kernel<<<(MTOK * DI / 4 + 255) / 256, 256>>>(
        xz16, conv_w, conv_b, uconv16);

    // 4. x_proj split-K=4 -> partials; reduce -> xdbl fp32 + dt16
    gemm_lm<32, 96, 2, 3, 0><<<dim3(1, MTOK / 32, XKSPLIT), 192>>>(
        uconv16, DI / 2, wx16, DI / 2, xpart, XDBL_W, DI / XKSPLIT, nullptr,
        nullptr, 0, (DI / XKSPLIT) / 2, (size_t)MTOK * XDBL_W);
    xproj_reduce<<<(MTOK * XDBL_W / 2 + 255) / 256, 256>>>(xpart, xdbl, dt16);

    // 5. dt_proj -> delta fp32, 64x64 warp tile
    gemm_lm<128, 128, 2, 2, 1><<<dim3(DI / 128, MTOK / 128), 128>>>(
        dt16, DTR / 2, wdt16, DTR / 2, delta, DI, DTR, dt_proj_b,
        nullptr, 0, 0, 0);

    // 6. chunked selective scan -> y16 (U=8 unroll)
    {
        int nw = BB * (DI / 2) * GCH;
        scan_p1<<<(nw * 32) / 256, 256>>>(delta, uconv16, xdbl, A_log, Ac, Hc);
        scan_p2<<<(BB * DI * DS + 255) / 256, 256>>>(Ac, Hc, Ci);
        scan_p3<<<(nw * 32) / 256, 256>>>(delta, uconv16, xdbl, xz16,
                                          A_log, Dp, Ci, y16);
    }

    // 7. out_proj + residual -> out, 64x64 warp tile
    gemm_lm<128, 128, 2, 2, 2><<<dim3(DM / 128, MTOK / 128), 128>>>(
        (const uint32_t*)y16, DI / 2, wout16, DI / 2, out, DM, DI, x,
        nullptr, 0, 0, 0);
}

// round 16
// speedup vs baseline: 1.0702x; 1.0702x over previous
#include <cuda_runtime.h>
#include <cuda_bf16.h>
#include <math.h>
#include <stdint.h>

// ---------------- problem constants ----------------
#define BB   2
#define LL   2048
#define DM   1024
#define DI   2048
#define DTR  64
#define DS   16
#define MTOK (BB * LL)   // 4096 tokens
#define XDBL_W 96
#define GCH  16          // scan chunks
#define CHLEN (LL / GCH) // 128
#define XKSPLIT 4

// ---------------- scratch ----------------
__device__ float    g_xdbl [(size_t)MTOK * XDBL_W];
__device__ float    g_delta[(size_t)MTOK * DI];
__device__ float    g_xpart[(size_t)XKSPLIT * MTOK * XDBL_W];
__device__ uint32_t g_xn16   [(size_t)MTOK * DM / 2];
__device__ uint32_t g_xz16   [(size_t)MTOK * 2 * DI / 2];   // u|z bf16 packed
__device__ uint32_t g_uconv16[(size_t)MTOK * DI / 2];
__device__ uint32_t g_dt16   [(size_t)MTOK * DTR / 2];
__device__ __nv_bfloat16 g_y16[(size_t)MTOK * DI];
__device__ uint32_t g_win16  [(size_t)2 * DI * DM / 2];
__device__ uint32_t g_wx16   [(size_t)XDBL_W * DI / 2];
__device__ uint32_t g_wdt16  [(size_t)DI * DTR / 2];
__device__ uint32_t g_wout16 [(size_t)DM * DI / 2];
// scan carries: [(b*DI+dd)*DS+n][GCH]
__device__ float g_Ac[(size_t)BB * DI * DS * GCH];
__device__ float g_Hc[(size_t)BB * DI * DS * GCH];

// ---------------- helpers ----------------
__device__ __forceinline__ float softplus_f(float v) {
    return (v > 20.f) ? v : log1pf(__expf(v));
}
__device__ __forceinline__ float silu_f(float v) {
    return v * (1.f / (1.f + __expf(-v)));
}
__device__ __forceinline__ uint32_t packbf(float lo, float hi) {
    __nv_bfloat162 h(__float2bfloat16_rn(lo), __float2bfloat16_rn(hi));
    return *reinterpret_cast<uint32_t*>(&h);
}
__device__ __forceinline__ float2 unpk(uint32_t v) {
    __nv_bfloat162 h = *reinterpret_cast<__nv_bfloat162*>(&v);
    return make_float2(__bfloat162float(h.x), __bfloat162float(h.y));
}
__device__ __forceinline__ void mma_bf16(float* c, const uint32_t* a, const uint32_t* b) {
    asm volatile("mma.sync.aligned.m16n8k16.row.col.f32.bf16.bf16.f32 "
                 "{%0,%1,%2,%3}, {%4,%5,%6,%7}, {%8,%9}, {%0,%1,%2,%3};"
                 : "+f"(c[0]), "+f"(c[1]), "+f"(c[2]), "+f"(c[3])
                 : "r"(a[0]), "r"(a[1]), "r"(a[2]), "r"(a[3]),
                   "r"(b[0]), "r"(b[1]));
}
__device__ __forceinline__ void cp16(void* dst, const void* src) {
    uint32_t d = (uint32_t)__cvta_generic_to_shared(dst);
    asm volatile("cp.async.cg.shared.global [%0], [%1], 16;" :: "r"(d), "l"(src));
}
__device__ __forceinline__ uint32_t smem_u32(const void* p) {
    uint32_t a;
    asm("{ .reg .u64 t; cvta.to.shared.u64 t, %1; cvt.u32.u64 %0, t; }"
        : "=r"(a) : "l"(p));
    return a;
}
__device__ __forceinline__ void ldm_x4(uint32_t* r, uint32_t addr) {
    asm volatile("ldmatrix.sync.aligned.m8n8.x4.shared.b16 {%0,%1,%2,%3}, [%4];"
        : "=r"(r[0]), "=r"(r[1]), "=r"(r[2]), "=r"(r[3]) : "r"(addr));
}

// ---------------- one fused weight conversion ----------------
#define CN1 (2 * DI * DM / 2)
#define CN2 (XDBL_W * DI / 2)
#define CN3 (DI * DTR / 2)
#define CN4 (DM * DI / 2)
__global__ void convert_all(const float* __restrict__ w1, const float* __restrict__ w2,
                            const float* __restrict__ w3, const float* __restrict__ w4,
                            uint32_t* __restrict__ d1, uint32_t* __restrict__ d2,
                            uint32_t* __restrict__ d3, uint32_t* __restrict__ d4) {
    int i = blockIdx.x * blockDim.x + threadIdx.x;
    const float2* s; uint32_t* d; int j;
    if (i < CN1)                      { s = (const float2*)w1; d = d1; j = i; }
    else if (i < CN1 + CN2)           { s = (const float2*)w2; d = d2; j = i - CN1; }
    else if (i < CN1 + CN2 + CN3)     { s = (const float2*)w3; d = d3; j = i - CN1 - CN2; }
    else if (i < CN1 + CN2 + CN3 + CN4){ s = (const float2*)w4; d = d4; j = i - CN1 - CN2 - CN3; }
    else return;
    float2 v = s[j];
    d[j] = packbf(v.x, v.y);
}

// ---------------- LayerNorm -> bf16 packed ----------------
__global__ void ln_kernel(const float* __restrict__ x,
                          const float* __restrict__ w,
                          const float* __restrict__ b,
                          uint32_t* __restrict__ out16) {
    const int row = blockIdx.x;
    const int tid = threadIdx.x;
    const float4* xr = (const float4*)(x + (size_t)row * DM);
    float4 v = xr[tid];

    float s  = v.x + v.y + v.z + v.w;
    float s2 = v.x * v.x + v.y * v.y + v.z * v.z + v.w * v.w;

    __shared__ float shs[8], shs2[8];
    #pragma unroll
    for (int o = 16; o > 0; o >>= 1) {
        s  += __shfl_down_sync(0xffffffffu, s,  o);
        s2 += __shfl_down_sync(0xffffffffu, s2, o);
    }
    if ((tid & 31) == 0) { shs[tid >> 5] = s; shs2[tid >> 5] = s2; }
    __syncthreads();
    float mu = 0.f, m2 = 0.f;
    #pragma unroll
    for (int i = 0; i < 8; i++) { mu += shs[i]; m2 += shs2[i]; }
    mu *= (1.f / DM);
    m2 *= (1.f / DM);
    float inv = rsqrtf(m2 - mu * mu + 1e-5f);

    float4 wv = ((const float4*)w)[tid];
    float4 bv = ((const float4*)b)[tid];
    uint2 p;
    p.x = packbf((v.x - mu) * inv * wv.x + bv.x, (v.y - mu) * inv * wv.y + bv.y);
    p.y = packbf((v.z - mu) * inv * wv.z + bv.z, (v.w - mu) * inv * wv.w + bv.w);
    ((uint2*)(out16 + (size_t)row * (DM / 2)))[tid] = p;
}

// ---------------- bf16 mma.sync GEMM (ldmatrix, split-K, 3-stage) -----------
// EPI: 0 plain fp32, 1 softplus(v+aux[n]) fp32, 2 v+aux[m*ldc+n],
//      4 bf16-only -> Cb
template<int BM, int BN, int WM, int WN, int EPI>
__global__ __launch_bounds__(WM * WN * 32)
void gemm_lm(const uint32_t* __restrict__ A, int ldaU,
             const uint32_t* __restrict__ W, int ldwU,
             float* __restrict__ C, int ldc, int K,
             const float* __restrict__ aux,
             uint32_t* __restrict__ Cb, int ldcbU,
             int kSliceU, size_t cSliceF) {
    constexpr int NTHR = WM * WN * 32;
    constexpr int BK2 = 16;
    constexpr int STR = 20;
    constexpr int S = 3;
    constexpr int WARP_M = BM / WM;
    constexpr int WARP_N = BN / WN;
    constexpr int MT = WARP_M / 16;
    constexpr int NT = WARP_N / 8;
    static_assert(NT % 2 == 0, "NT must be even for x4 B loads");

    __shared__ __align__(16) uint32_t As[S][BM][STR];
    __shared__ __align__(16) uint32_t Bs[S][BN][STR];

    const int kz = blockIdx.z;
    A += (size_t)kz * kSliceU;
    W += (size_t)kz * kSliceU;
    C += (size_t)kz * cSliceF;

    const int tid  = threadIdx.x;
    const int lane = tid & 31;
    const int warp = tid >> 5;
    const int gid  = lane >> 2;
    const int tig  = lane & 3;

    const int bm0 = blockIdx.y * BM;
    const int bn0 = blockIdx.x * BN;
    const int wm0 = (warp / WN) * WARP_M;
    const int wn0 = (warp % WN) * WARP_N;

    float acc[MT][NT][4];
    #pragma unroll
    for (int i = 0; i < MT; i++)
        #pragma unroll
        for (int j = 0; j < NT; j++)
            #pragma unroll
            for (int e = 0; e < 4; e++) acc[i][j][e] = 0.f;

    auto load_tile = [&](int buf, int kt) {
        const int k0 = kt * BK2;
        #pragma unroll
        for (int s = tid; s < BM * 4; s += NTHR) {
            int r = s >> 2, c = (s & 3) * 4;
            cp16(&As[buf][r][c], A + (size_t)(bm0 + r) * ldaU + k0 + c);
        }
        #pragma unroll
        for (int s = tid; s < BN * 4; s += NTHR) {
            int r = s >> 2, c = (s & 3) * 4;
            cp16(&Bs[buf][r][c], W + (size_t)(bn0 + r) * ldwU + k0 + c);
        }
        asm volatile("cp.async.commit_group;");
    };

    const int nkt = K / 32;
    load_tile(0, 0);
    if (nkt > 1) load_tile(1, 1);

    const uint32_t a_row = (uint32_t)(lane & 15);
    const uint32_t a_col = (uint32_t)((lane >> 4) << 2);
    const uint32_t b_row = (uint32_t)((lane & 7) + ((lane >> 4) << 3));
    const uint32_t b_col = (uint32_t)(((lane >> 3) & 1) << 2);

    for (int kt = 0; kt < nkt; kt++) {
        const int buf = kt % S;
        if (kt + 1 < nkt) asm volatile("cp.async.wait_group 1;");
        else              asm volatile("cp.async.wait_group 0;");
        __syncthreads();
        if (kt + 2 < nkt) load_tile((kt + 2) % S, kt + 2);

        const uint32_t abase = smem_u32(&As[buf][0][0]);
        const uint32_t bbase = smem_u32(&Bs[buf][0][0]);

        #pragma unroll
        for (int ks = 0; ks < 2; ks++) {
            uint32_t af[MT][4];
            uint32_t bf[NT][2];
            #pragma unroll
            for (int mt = 0; mt < MT; mt++) {
                uint32_t r = (uint32_t)(wm0 + mt * 16) + a_row;
                ldm_x4(af[mt], abase + (r * STR + ks * 8 + a_col) * 4);
            }
            #pragma unroll
            for (int ip = 0; ip < NT / 2; ip++) {
                uint32_t r = (uint32_t)(wn0 + ip * 16) + b_row;
                uint32_t q[4];
                ldm_x4(q, bbase + (r * STR + ks * 8 + b_col) * 4);
                bf[2 * ip][0]     = q[0]; bf[2 * ip][1]     = q[1];
                bf[2 * ip + 1][0] = q[2]; bf[2 * ip + 1][1] = q[3];
            }
            #pragma unroll
            for (int mt = 0; mt < MT; mt++)
                #pragma unroll
                for (int nt = 0; nt < NT; nt++)
                    mma_bf16(acc[mt][nt], af[mt], bf[nt]);
        }
    }

    #pragma unroll
    for (int mt = 0; mt < MT; mt++) {
        int r0 = bm0 + wm0 + mt * 16 + gid;
        int r1 = r0 + 8;
        #pragma unroll
        for (int nt = 0; nt < NT; nt++) {
            int cn = bn0 + wn0 + nt * 8 + 2 * tig;
            float v0 = acc[mt][nt][0], v1 = acc[mt][nt][1];
            float v2 = acc[mt][nt][2], v3 = acc[mt][nt][3];
            if (EPI == 4) {
                Cb[(size_t)r0 * ldcbU + cn / 2] = packbf(v0, v1);
                Cb[(size_t)r1 * ldcbU + cn / 2] = packbf(v2, v3);
                continue;
            }
            if (EPI == 1) {
                v0 = softplus_f(v0 + aux[cn]);   v1 = softplus_f(v1 + aux[cn + 1]);
                v2 = softplus_f(v2 + aux[cn]);   v3 = softplus_f(v3 + aux[cn + 1]);
            }
            if (EPI == 2) {
                v0 += aux[(size_t)r0 * ldc + cn];  v1 += aux[(size_t)r0 * ldc + cn + 1];
                v2 += aux[(size_t)r1 * ldc + cn];  v3 += aux[(size_t)r1 * ldc + cn + 1];
            }
            *(float2*)(C + (size_t)r0 * ldc + cn) = make_float2(v0, v1);
            *(float2*)(C + (size_t)r1 * ldc + cn) = make_float2(v2, v3);
        }
    }
}

// ---------------- x_proj split-K reduce: partials -> xdbl + dt16 ------------
__global__ void xproj_reduce(const float* __restrict__ parts,
                             float* __restrict__ xdbl,
                             uint32_t* __restrict__ dt16) {
    int idx = blockIdx.x * blockDim.x + threadIdx.x;     // float2 index
    if (idx >= MTOK * XDBL_W / 2) return;
    float2 s = make_float2(0.f, 0.f);
    #pragma unroll
    for (int z = 0; z < XKSPLIT; z++) {
        float2 v = ((const float2*)(parts + (size_t)z * MTOK * XDBL_W))[idx];
        s.x += v.x; s.y += v.y;
    }
    ((float2*)xdbl)[idx] = s;
    int col2 = idx % (XDBL_W / 2);
    if (col2 < DTR / 2) {
        int row = idx / (XDBL_W / 2);
        dt16[(size_t)row * (DTR / 2) + col2] = packbf(s.x, s.y);
    }
}

// ---------------- causal conv(4) + bias + SiLU (bf16, 4 channels/thread) ---
__global__ void conv_silu_kernel(const uint32_t* __restrict__ xz16,
                                 const float* __restrict__ cw,
                                 const float* __restrict__ cb,
                                 uint32_t* __restrict__ out16) {
    int idx = blockIdx.x * blockDim.x + threadIdx.x;   // quad index (4 chans)
    if (idx >= MTOK * DI / 4) return;
    int q  = idx % (DI / 4);
    int d  = q * 4;
    int t  = idx / (DI / 4);
    int l  = t % LL;

    const uint2* up = (const uint2*)(xz16 + (size_t)t * (2 * DI / 2)) + q;
    const ptrdiff_t rowstride = (2 * DI / 2) / 2;
    uint2 z2 = make_uint2(0u, 0u);
    uint2 q0 = up[0];
    uint2 q1 = (l >= 1) ? up[-rowstride * 1] : z2;
    uint2 q2 = (l >= 2) ? up[-rowstride * 2] : z2;
    uint2 q3 = (l >= 3) ? up[-rowstride * 3] : z2;

    float2 c0a = unpk(q0.x), c0b = unpk(q0.y);
    float2 c1a = unpk(q1.x), c1b = unpk(q1.y);
    float2 c2a = unpk(q2.x), c2b = unpk(q2.y);
    float2 c3a = unpk(q3.x), c3b = unpk(q3.y);

    float4 w0 = *(const float4*)(cw + (size_t)(d + 0) * 4);
    float4 w1 = *(const float4*)(cw + (size_t)(d + 1) * 4);
    float4 w2 = *(const float4*)(cw + (size_t)(d + 2) * 4);
    float4 w3 = *(const float4*)(cw + (size_t)(d + 3) * 4);
    float4 bb = *(const float4*)(cb + d);

    float r0 = silu_f(w0.w * c0a.x + w0.z * c1a.x + w0.y * c2a.x + w0.x * c3a.x + bb.x);
    float r1 = silu_f(w1.w * c0a.y + w1.z * c1a.y + w1.y * c2a.y + w1.x * c3a.y + bb.y);
    float r2 = silu_f(w2.w * c0b.x + w2.z * c1b.x + w2.y * c2b.x + w2.x * c3b.x + bb.z);
    float r3 = silu_f(w3.w * c0b.y + w3.z * c1b.y + w3.y * c2b.y + w3.x * c3b.y + bb.w);

    uint2 o;
    o.x = packbf(r0, r1);
    o.y = packbf(r2, r3);
    ((uint2*)out16)[idx] = o;
}

// ---------------- chunked selective scan (p2 fused into p3, U=4) -----------
// p1 covers chunks 0..14 (chunk 15's carry outputs are never consumed).
__global__ void scan_p1(const float* __restrict__ delta,
                        const uint32_t* __restrict__ u16,
                        const float* __restrict__ xdbl,
                        const float* __restrict__ A_log,
                        float* __restrict__ gAc, float* __restrict__ gHc) {
    int gt   = blockIdx.x * blockDim.x + threadIdx.x;
    int w    = gt >> 5;
    int lane = gt & 31;
    if (w >= BB * (DI / 2) * (GCH - 1)) return;

    int pair = w & 1023;
    int b    = (w >> 10) & 1;
    int g    = w >> 11;                 // 0..14
    int hi   = lane >> 4;
    int dd   = pair * 2 + hi;
    int n    = lane & 15;
    int t0   = g * CHLEN;

    float Ad = -expf(A_log[dd * DS + n]);
    float h = 0.f, ap = 1.f;

    const size_t base_d = (size_t)(b * LL + t0) * DI + dd;
    const size_t base_u = (size_t)(b * LL + t0) * (DI / 2) + pair;
    const size_t base_x = (size_t)(b * LL + t0) * XDBL_W;

    constexpr int U = 4;
    float de[U], Bn[U];
    uint32_t uup[U];
    #pragma unroll
    for (int j = 0; j < U; j++) {
        de[j]  = delta[base_d + (size_t)j * DI];
        uup[j] = u16 [base_u + (size_t)j * (DI / 2)];
        Bn[j]  = xdbl[base_x + (size_t)j * XDBL_W + DTR + n];
    }
    for (int t = 0; t < CHLEN; t += U) {
        float cde[U], cuu[U], cBn[U];
        #pragma unroll
        for (int j = 0; j < U; j++) {
            cde[j] = de[j]; cBn[j] = Bn[j];
            float2 uv = unpk(uup[j]);
            cuu[j] = hi ? uv.y : uv.x;
        }
        if (t + U < CHLEN) {
            const size_t od = base_d + (size_t)(t + U) * DI;
            const size_t ou = base_u + (size_t)(t + U) * (DI / 2);
            const size_t ox = base_x + (size_t)(t + U) * XDBL_W;
            #pragma unroll
            for (int j = 0; j < U; j++) {
                de[j]  = delta[od + (size_t)j * DI];
                uup[j] = u16 [ou + (size_t)j * (DI / 2)];
                Bn[j]  = xdbl[ox + (size_t)j * XDBL_W + DTR + n];
            }
        }
        #pragma unroll
        for (int j = 0; j < U; j++) {
            float dA = __expf(cde[j] * Ad);
            h = fmaf(dA, h, cde[j] * cuu[j] * cBn[j]);
            ap *= dA;
        }
    }
    size_t idx = ((size_t)(b * DI + dd) * DS + n) * GCH + g;
    gAc[idx] = ap;
    gHc[idx] = h;
}

__global__ void scan_p3(const float* __restrict__ delta,
                        const uint32_t* __restrict__ u16,
                        const float* __restrict__ xdbl,
                        const uint32_t* __restrict__ xz16,
                        const float* __restrict__ A_log,
                        const float* __restrict__ Dp,
                        const float* __restrict__ gAc,
                        const float* __restrict__ gHc,
                        __nv_bfloat16* __restrict__ y16) {
    int gt   = blockIdx.x * blockDim.x + threadIdx.x;
    int w    = gt >> 5;
    int lane = gt & 31;
    if (w >= BB * (DI / 2) * GCH) return;

    int pair = w & 1023;
    int b    = (w >> 10) & 1;
    int g    = w >> 11;
    int hi   = lane >> 4;
    int dd   = pair * 2 + hi;
    int n    = lane & 15;
    int t0   = g * CHLEN;

    float Ad = -expf(A_log[dd * DS + n]);
    float Dd = Dp[dd];

    // carry-in: fold predecessors' (Ac, Hc). Loads are independent (preloaded
    // by the compiler into registers), then a <=15-deep fma chain.
    float h = 0.f;
    {
        const size_t cbase = ((size_t)(b * DI + dd) * DS + n) * GCH;
        for (int gg = 0; gg < g; gg++)
            h = fmaf(gAc[cbase + gg], h, gHc[cbase + gg]);
    }

    const size_t base_d = (size_t)(b * LL + t0) * DI + dd;
    const size_t base_u = (size_t)(b * LL + t0) * (DI / 2) + pair;
    const size_t base_x = (size_t)(b * LL + t0) * XDBL_W;
    const size_t base_z = (size_t)(b * LL + t0) * (2 * DI / 2) + DI / 2 + pair;

    constexpr int U = 4;
    float de[U], Bn[U], Cn[U];
    uint32_t uup[U], zzp[U];
    #pragma unroll
    for (int j = 0; j < U; j++) {
        de[j]  = delta[base_d + (size_t)j * DI];
        uup[j] = u16 [base_u + (size_t)j * (DI / 2)];
        Bn[j]  = xdbl[base_x + (size_t)j * XDBL_W + DTR + n];
        Cn[j]  = xdbl[base_x + (size_t)j * XDBL_W + DTR + DS + n];
        zzp[j] = xz16[base_z + (size_t)j * (2 * DI / 2)];
    }
    for (int t = 0; t < CHLEN; t += U) {
        float cde[U], cuu[U], cBn[U], cCn[U], czv[U];
        #pragma unroll
        for (int j = 0; j < U; j++) {
            float2 uv = unpk(uup[j]);
            float2 zv = unpk(zzp[j]);
            cde[j] = de[j];
            cuu[j] = hi ? uv.y : uv.x;
            czv[j] = hi ? zv.y : zv.x;
            cBn[j] = Bn[j];
            cCn[j] = Cn[j];
        }
        if (t + U < CHLEN) {
            const size_t od = base_d + (size_t)(t + U) * DI;
            const size_t ou = base_u + (size_t)(t + U) * (DI / 2);
            const size_t ox = base_x + (size_t)(t + U) * XDBL_W;
            const size_t oz = base_z + (size_t)(t + U) * (2 * DI / 2);
            #pragma unroll
            for (int j = 0; j < U; j++) {
                de[j]  = delta[od + (size_t)j * DI];
                uup[j] = u16 [ou + (size_t)j * (DI / 2)];
                Bn[j]  = xdbl[ox + (size_t)j * XDBL_W + DTR + n];
                Cn[j]  = xdbl[ox + (size_t)j * XDBL_W + DTR + DS + n];
                zzp[j] = xz16[oz + (size_t)j * (2 * DI / 2)];
            }
        }
        float yv[U];
        #pragma unroll
        for (int j = 0; j < U; j++) {
            float dA = __expf(cde[j] * Ad);
            h = fmaf(dA, h, cde[j] * cuu[j] * cBn[j]);
            yv[j] = h * cCn[j];
        }
        #pragma unroll
        for (int o = 8; o > 0; o >>= 1) {
            #pragma unroll
            for (int j = 0; j < U; j++)
                yv[j] += __shfl_xor_sync(0xffffffffu, yv[j], o);
        }
        if (n == 0) {
            #pragma unroll
            for (int j = 0; j < U; j++)
                y16[base_d + (size_t)(t + j) * DI] =
                    __float2bfloat16_rn((yv[j] + cuu[j] * Dd) * silu_f(czv[j]));
        }
    }
}

// ---------------- launch ----------------------------------------------------
extern "C" void kernel_launch(void* const* d_in, const int* in_sizes, int n_in,
                              void* d_out, int out_size) {
    const float* x         = (const float*)d_in[0];
    const float* ln_w      = (const float*)d_in[1];
    const float* ln_b      = (const float*)d_in[2];
    const float* in_proj_w = (const float*)d_in[3];
    const float* conv_w    = (const float*)d_in[4];
    const float* conv_b    = (const float*)d_in[5];
    const float* x_proj_w  = (const float*)d_in[6];
    const float* dt_proj_w = (const float*)d_in[7];
    const float* dt_proj_b = (const float*)d_in[8];
    const float* A_log     = (const float*)d_in[9];
    const float* Dp        = (const float*)d_in[10];
    const float* out_pw    = (const float*)d_in[11];
    float* out = (float*)d_out;

    float *xdbl, *delta, *xpart, *Ac, *Hc;
    uint32_t *xn16, *xz16, *uconv16, *dt16, *win16, *wx16, *wdt16, *wout16;
    __nv_bfloat16* y16;
    cudaGetSymbolAddress((void**)&xdbl,    g_xdbl);
    cudaGetSymbolAddress((void**)&delta,   g_delta);
    cudaGetSymbolAddress((void**)&xpart,   g_xpart);
    cudaGetSymbolAddress((void**)&xn16,    g_xn16);
    cudaGetSymbolAddress((void**)&xz16,    g_xz16);
    cudaGetSymbolAddress((void**)&uconv16, g_uconv16);
    cudaGetSymbolAddress((void**)&dt16,    g_dt16);
    cudaGetSymbolAddress((void**)&y16,     g_y16);
    cudaGetSymbolAddress((void**)&win16,   g_win16);
    cudaGetSymbolAddress((void**)&wx16,    g_wx16);
    cudaGetSymbolAddress((void**)&wdt16,   g_wdt16);
    cudaGetSymbolAddress((void**)&wout16,  g_wout16);
    cudaGetSymbolAddress((void**)&Ac,      g_Ac);
    cudaGetSymbolAddress((void**)&Hc,      g_Hc);

    // 0. fused weight conversion
    {
        int tot = CN1 + CN2 + CN3 + CN4;
        convert_all<<<(tot + 255) / 256, 256>>>(
            in_proj_w, x_proj_w, dt_proj_w, out_pw, win16, wx16, wdt16, wout16);
    }

    // 1. LayerNorm -> xn16
    ln_kernel<<<MTOK, 256>>>(x, ln_w, ln_b, xn16);

    // 2. in_proj -> xz16 (bf16), 64x64 warp tile
    gemm_lm<128, 128, 2, 2, 4><<<dim3((2 * DI) / 128, MTOK / 128), 128>>>(
        xn16, DM / 2, win16, DM / 2, nullptr, 0, DM, nullptr,
        xz16, 2 * DI / 2, 0, 0);

    // 3. conv + SiLU -> uconv16 (4 channels/thread)
    conv_silu_kernel<<<(MTOK * DI / 4 + 255) / 256, 256>>>(
        xz16, conv_w, conv_b, uconv16);

    // 4. x_proj split-K=4 -> partials; reduce -> xdbl fp32 + dt16
    gemm_lm<32, 96, 2, 3, 0><<<dim3(1, MTOK / 32, XKSPLIT), 192>>>(
        uconv16, DI / 2, wx16, DI / 2, xpart, XDBL_W, DI / XKSPLIT, nullptr,
        nullptr, 0, (DI / XKSPLIT) / 2, (size_t)MTOK * XDBL_W);
    xproj_reduce<<<(MTOK * XDBL_W / 2 + 255) / 256, 256>>>(xpart, xdbl, dt16);

    // 5. dt_proj -> delta fp32, 64x64 warp tile
    gemm_lm<128, 128, 2, 2, 1><<<dim3(DI / 128, MTOK / 128), 128>>>(
        dt16, DTR / 2, wdt16, DTR / 2, delta, DI, DTR, dt_proj_b,
        nullptr, 0, 0, 0);

    // 6. chunked selective scan -> y16 (carry fold fused into p3)
    {
        int nw1 = BB * (DI / 2) * (GCH - 1);
        scan_p1<<<(nw1 * 32) / 256, 256>>>(delta, uconv16, xdbl, A_log, Ac, Hc);
        int nw3 = BB * (DI / 2) * GCH;
        scan_p3<<<(nw3 * 32) / 256, 256>>>(delta, uconv16, xdbl, xz16,
                                           A_log, Dp, Ac, Hc, y16);
    }

    // 7. out_proj + residual -> out, 64x64 warp tile
    gemm_lm<128, 128, 2, 2, 2><<<dim3(DM / 128, MTOK / 128), 128>>>(
        (const uint32_t*)y16, DI / 2, wout16, DI / 2, out, DM, DI, x,
        nullptr, 0, 0, 0);
}

// round 17
// speedup vs baseline: 1.0825x; 1.0115x over previous
#include <cuda_runtime.h>
#include <cuda_bf16.h>
#include <math.h>
#include <stdint.h>

// ---------------- problem constants ----------------
#define BB   2
#define LL   2048
#define DM   1024
#define DI   2048
#define DTR  64
#define DS   16
#define MTOK (BB * LL)   // 4096 tokens
#define XDBL_W 96
#define GCH  16          // scan chunks
#define CHLEN (LL / GCH) // 128
#define XKSPLIT 4

// ---------------- scratch ----------------
__device__ float    g_xdbl [(size_t)MTOK * XDBL_W];
__device__ float    g_delta[(size_t)MTOK * DI];
__device__ float    g_xpart[(size_t)XKSPLIT * MTOK * XDBL_W];
__device__ uint32_t g_xn16   [(size_t)MTOK * DM / 2];
__device__ uint32_t g_xz16   [(size_t)MTOK * 2 * DI / 2];   // u|z bf16 packed
__device__ uint32_t g_uconv16[(size_t)MTOK * DI / 2];
__device__ uint32_t g_dt16   [(size_t)MTOK * DTR / 2];
__device__ __nv_bfloat16 g_y16[(size_t)MTOK * DI];
__device__ uint32_t g_win16  [(size_t)2 * DI * DM / 2];
__device__ uint32_t g_wx16   [(size_t)XDBL_W * DI / 2];
__device__ uint32_t g_wdt16  [(size_t)DI * DTR / 2];
__device__ uint32_t g_wout16 [(size_t)DM * DI / 2];
// scan carries: [(b*DI+dd)*DS+n][GCH]
__device__ float g_Ac[(size_t)BB * DI * DS * GCH];
__device__ float g_Hc[(size_t)BB * DI * DS * GCH];
__device__ float g_Ci[(size_t)BB * DI * DS * GCH];

// ---------------- helpers ----------------
__device__ __forceinline__ float softplus_f(float v) {
    return (v > 20.f) ? v : log1pf(__expf(v));
}
__device__ __forceinline__ float silu_f(float v) {
    return v * (1.f / (1.f + __expf(-v)));
}
__device__ __forceinline__ uint32_t packbf(float lo, float hi) {
    __nv_bfloat162 h(__float2bfloat16_rn(lo), __float2bfloat16_rn(hi));
    return *reinterpret_cast<uint32_t*>(&h);
}
__device__ __forceinline__ float2 unpk(uint32_t v) {
    __nv_bfloat162 h = *reinterpret_cast<__nv_bfloat162*>(&v);
    return make_float2(__bfloat162float(h.x), __bfloat162float(h.y));
}
__device__ __forceinline__ void mma_bf16(float* c, const uint32_t* a, const uint32_t* b) {
    asm volatile("mma.sync.aligned.m16n8k16.row.col.f32.bf16.bf16.f32 "
                 "{%0,%1,%2,%3}, {%4,%5,%6,%7}, {%8,%9}, {%0,%1,%2,%3};"
                 : "+f"(c[0]), "+f"(c[1]), "+f"(c[2]), "+f"(c[3])
                 : "r"(a[0]), "r"(a[1]), "r"(a[2]), "r"(a[3]),
                   "r"(b[0]), "r"(b[1]));
}
__device__ __forceinline__ void cp16(void* dst, const void* src) {
    uint32_t d = (uint32_t)__cvta_generic_to_shared(dst);
    asm volatile("cp.async.cg.shared.global [%0], [%1], 16;" :: "r"(d), "l"(src));
}
__device__ __forceinline__ uint32_t smem_u32(const void* p) {
    uint32_t a;
    asm("{ .reg .u64 t; cvta.to.shared.u64 t, %1; cvt.u32.u64 %0, t; }"
        : "=r"(a) : "l"(p));
    return a;
}
__device__ __forceinline__ void ldm_x4(uint32_t* r, uint32_t addr) {
    asm volatile("ldmatrix.sync.aligned.m8n8.x4.shared.b16 {%0,%1,%2,%3}, [%4];"
        : "=r"(r[0]), "=r"(r[1]), "=r"(r[2]), "=r"(r[3]) : "r"(addr));
}

// ---------------- fused LN + weight conversion (one launch) -----------------
#define CN1 (2 * DI * DM / 2)
#define CN2 (XDBL_W * DI / 2)
#define CN3 (DI * DTR / 2)
#define CN4 (DM * DI / 2)
#define CNT (CN1 + CN2 + CN3 + CN4)
#define CVT_BLOCKS ((CNT + 255) / 256)

__global__ __launch_bounds__(256)
void ln_convert_kernel(const float* __restrict__ x,
                       const float* __restrict__ lw,
                       const float* __restrict__ lb,
                       uint32_t* __restrict__ out16,
                       const float* __restrict__ w1, const float* __restrict__ w2,
                       const float* __restrict__ w3, const float* __restrict__ w4,
                       uint32_t* __restrict__ d1, uint32_t* __restrict__ d2,
                       uint32_t* __restrict__ d3, uint32_t* __restrict__ d4) {
    const int tid = threadIdx.x;
    if (blockIdx.x >= MTOK) {
        // ---- weight conversion part ----
        int i = (blockIdx.x - MTOK) * 256 + tid;
        const float2* s; uint32_t* d; int j;
        if (i < CN1)                       { s = (const float2*)w1; d = d1; j = i; }
        else if (i < CN1 + CN2)            { s = (const float2*)w2; d = d2; j = i - CN1; }
        else if (i < CN1 + CN2 + CN3)      { s = (const float2*)w3; d = d3; j = i - CN1 - CN2; }
        else if (i < CNT)                  { s = (const float2*)w4; d = d4; j = i - CN1 - CN2 - CN3; }
        else return;
        float2 v = s[j];
        d[j] = packbf(v.x, v.y);
        return;
    }
    // ---- LayerNorm part ----
    const int row = blockIdx.x;
    const float4* xr = (const float4*)(x + (size_t)row * DM);
    float4 v = xr[tid];

    float s  = v.x + v.y + v.z + v.w;
    float s2 = v.x * v.x + v.y * v.y + v.z * v.z + v.w * v.w;

    __shared__ float shs[8], shs2[8];
    #pragma unroll
    for (int o = 16; o > 0; o >>= 1) {
        s  += __shfl_down_sync(0xffffffffu, s,  o);
        s2 += __shfl_down_sync(0xffffffffu, s2, o);
    }
    if ((tid & 31) == 0) { shs[tid >> 5] = s; shs2[tid >> 5] = s2; }
    __syncthreads();
    float mu = 0.f, m2 = 0.f;
    #pragma unroll
    for (int i = 0; i < 8; i++) { mu += shs[i]; m2 += shs2[i]; }
    mu *= (1.f / DM);
    m2 *= (1.f / DM);
    float inv = rsqrtf(m2 - mu * mu + 1e-5f);

    float4 wv = ((const float4*)lw)[tid];
    float4 bv = ((const float4*)lb)[tid];
    uint2 p;
    p.x = packbf((v.x - mu) * inv * wv.x + bv.x, (v.y - mu) * inv * wv.y + bv.y);
    p.y = packbf((v.z - mu) * inv * wv.z + bv.z, (v.w - mu) * inv * wv.w + bv.w);
    ((uint2*)(out16 + (size_t)row * (DM / 2)))[tid] = p;
}

// ---------------- bf16 mma.sync GEMM (ldmatrix, split-K, 3-stage) -----------
// EPI: 0 plain fp32, 1 softplus(v+aux[n]) fp32, 2 v+aux[m*ldc+n],
//      4 bf16-only -> Cb
template<int BM, int BN, int WM, int WN, int EPI>
__global__ __launch_bounds__(WM * WN * 32)
void gemm_lm(const uint32_t* __restrict__ A, int ldaU,
             const uint32_t* __restrict__ W, int ldwU,
             float* __restrict__ C, int ldc, int K,
             const float* __restrict__ aux,
             uint32_t* __restrict__ Cb, int ldcbU,
             int kSliceU, size_t cSliceF) {
    constexpr int NTHR = WM * WN * 32;
    constexpr int BK2 = 16;
    constexpr int STR = 20;
    constexpr int S = 3;
    constexpr int WARP_M = BM / WM;
    constexpr int WARP_N = BN / WN;
    constexpr int MT = WARP_M / 16;
    constexpr int NT = WARP_N / 8;
    static_assert(NT % 2 == 0, "NT must be even for x4 B loads");

    __shared__ __align__(16) uint32_t As[S][BM][STR];
    __shared__ __align__(16) uint32_t Bs[S][BN][STR];

    const int kz = blockIdx.z;
    A += (size_t)kz * kSliceU;
    W += (size_t)kz * kSliceU;
    C += (size_t)kz * cSliceF;

    const int tid  = threadIdx.x;
    const int lane = tid & 31;
    const int warp = tid >> 5;
    const int gid  = lane >> 2;
    const int tig  = lane & 3;

    const int bm0 = blockIdx.y * BM;
    const int bn0 = blockIdx.x * BN;
    const int wm0 = (warp / WN) * WARP_M;
    const int wn0 = (warp % WN) * WARP_N;

    float acc[MT][NT][4];
    #pragma unroll
    for (int i = 0; i < MT; i++)
        #pragma unroll
        for (int j = 0; j < NT; j++)
            #pragma unroll
            for (int e = 0; e < 4; e++) acc[i][j][e] = 0.f;

    auto load_tile = [&](int buf, int kt) {
        const int k0 = kt * BK2;
        #pragma unroll
        for (int s = tid; s < BM * 4; s += NTHR) {
            int r = s >> 2, c = (s & 3) * 4;
            cp16(&As[buf][r][c], A + (size_t)(bm0 + r) * ldaU + k0 + c);
        }
        #pragma unroll
        for (int s = tid; s < BN * 4; s += NTHR) {
            int r = s >> 2, c = (s & 3) * 4;
            cp16(&Bs[buf][r][c], W + (size_t)(bn0 + r) * ldwU + k0 + c);
        }
        asm volatile("cp.async.commit_group;");
    };

    const int nkt = K / 32;
    load_tile(0, 0);
    if (nkt > 1) load_tile(1, 1);

    const uint32_t a_row = (uint32_t)(lane & 15);
    const uint32_t a_col = (uint32_t)((lane >> 4) << 2);
    const uint32_t b_row = (uint32_t)((lane & 7) + ((lane >> 4) << 3));
    const uint32_t b_col = (uint32_t)(((lane >> 3) & 1) << 2);

    for (int kt = 0; kt < nkt; kt++) {
        const int buf = kt % S;
        if (kt + 1 < nkt) asm volatile("cp.async.wait_group 1;");
        else              asm volatile("cp.async.wait_group 0;");
        __syncthreads();
        if (kt + 2 < nkt) load_tile((kt + 2) % S, kt + 2);

        const uint32_t abase = smem_u32(&As[buf][0][0]);
        const uint32_t bbase = smem_u32(&Bs[buf][0][0]);

        #pragma unroll
        for (int ks = 0; ks < 2; ks++) {
            uint32_t af[MT][4];
            uint32_t bf[NT][2];
            #pragma unroll
            for (int mt = 0; mt < MT; mt++) {
                uint32_t r = (uint32_t)(wm0 + mt * 16) + a_row;
                ldm_x4(af[mt], abase + (r * STR + ks * 8 + a_col) * 4);
            }
            #pragma unroll
            for (int ip = 0; ip < NT / 2; ip++) {
                uint32_t r = (uint32_t)(wn0 + ip * 16) + b_row;
                uint32_t q[4];
                ldm_x4(q, bbase + (r * STR + ks * 8 + b_col) * 4);
                bf[2 * ip][0]     = q[0]; bf[2 * ip][1]     = q[1];
                bf[2 * ip + 1][0] = q[2]; bf[2 * ip + 1][1] = q[3];
            }
            #pragma unroll
            for (int mt = 0; mt < MT; mt++)
                #pragma unroll
                for (int nt = 0; nt < NT; nt++)
                    mma_bf16(acc[mt][nt], af[mt], bf[nt]);
        }
    }

    #pragma unroll
    for (int mt = 0; mt < MT; mt++) {
        int r0 = bm0 + wm0 + mt * 16 + gid;
        int r1 = r0 + 8;
        #pragma unroll
        for (int nt = 0; nt < NT; nt++) {
            int cn = bn0 + wn0 + nt * 8 + 2 * tig;
            float v0 = acc[mt][nt][0], v1 = acc[mt][nt][1];
            float v2 = acc[mt][nt][2], v3 = acc[mt][nt][3];
            if (EPI == 4) {
                Cb[(size_t)r0 * ldcbU + cn / 2] = packbf(v0, v1);
                Cb[(size_t)r1 * ldcbU + cn / 2] = packbf(v2, v3);
                continue;
            }
            if (EPI == 1) {
                v0 = softplus_f(v0 + aux[cn]);   v1 = softplus_f(v1 + aux[cn + 1]);
                v2 = softplus_f(v2 + aux[cn]);   v3 = softplus_f(v3 + aux[cn + 1]);
            }
            if (EPI == 2) {
                v0 += aux[(size_t)r0 * ldc + cn];  v1 += aux[(size_t)r0 * ldc + cn + 1];
                v2 += aux[(size_t)r1 * ldc + cn];  v3 += aux[(size_t)r1 * ldc + cn + 1];
            }
            *(float2*)(C + (size_t)r0 * ldc + cn) = make_float2(v0, v1);
            *(float2*)(C + (size_t)r1 * ldc + cn) = make_float2(v2, v3);
        }
    }
}

// ---------------- x_proj split-K reduce: partials -> xdbl + dt16 ------------
__global__ void xproj_reduce(const float* __restrict__ parts,
                             float* __restrict__ xdbl,
                             uint32_t* __restrict__ dt16) {
    int idx = blockIdx.x * blockDim.x + threadIdx.x;     // float2 index
    if (idx >= MTOK * XDBL_W / 2) return;
    float2 s = make_float2(0.f, 0.f);
    #pragma unroll
    for (int z = 0; z < XKSPLIT; z++) {
        float2 v = ((const float2*)(parts + (size_t)z * MTOK * XDBL_W))[idx];
        s.x += v.x; s.y += v.y;
    }
    ((float2*)xdbl)[idx] = s;
    int col2 = idx % (XDBL_W / 2);
    if (col2 < DTR / 2) {
        int row = idx / (XDBL_W / 2);
        dt16[(size_t)row * (DTR / 2) + col2] = packbf(s.x, s.y);
    }
}

// ---------------- causal conv(4) + bias + SiLU (bf16, 4 channels/thread) ---
__global__ void conv_silu_kernel(const uint32_t* __restrict__ xz16,
                                 const float* __restrict__ cw,
                                 const float* __restrict__ cb,
                                 uint32_t* __restrict__ out16) {
    int idx = blockIdx.x * blockDim.x + threadIdx.x;   // quad index (4 chans)
    if (idx >= MTOK * DI / 4) return;
    int q  = idx % (DI / 4);
    int d  = q * 4;
    int t  = idx / (DI / 4);
    int l  = t % LL;

    const uint2* up = (const uint2*)(xz16 + (size_t)t * (2 * DI / 2)) + q;
    const ptrdiff_t rowstride = (2 * DI / 2) / 2;
    uint2 z2 = make_uint2(0u, 0u);
    uint2 q0 = up[0];
    uint2 q1 = (l >= 1) ? up[-rowstride * 1] : z2;
    uint2 q2 = (l >= 2) ? up[-rowstride * 2] : z2;
    uint2 q3 = (l >= 3) ? up[-rowstride * 3] : z2;

    float2 c0a = unpk(q0.x), c0b = unpk(q0.y);
    float2 c1a = unpk(q1.x), c1b = unpk(q1.y);
    float2 c2a = unpk(q2.x), c2b = unpk(q2.y);
    float2 c3a = unpk(q3.x), c3b = unpk(q3.y);

    float4 w0 = *(const float4*)(cw + (size_t)(d + 0) * 4);
    float4 w1 = *(const float4*)(cw + (size_t)(d + 1) * 4);
    float4 w2 = *(const float4*)(cw + (size_t)(d + 2) * 4);
    float4 w3 = *(const float4*)(cw + (size_t)(d + 3) * 4);
    float4 bb = *(const float4*)(cb + d);

    float r0 = silu_f(w0.w * c0a.x + w0.z * c1a.x + w0.y * c2a.x + w0.x * c3a.x + bb.x);
    float r1 = silu_f(w1.w * c0a.y + w1.z * c1a.y + w1.y * c2a.y + w1.x * c3a.y + bb.y);
    float r2 = silu_f(w2.w * c0b.x + w2.z * c1b.x + w2.y * c2b.x + w2.x * c3b.x + bb.z);
    float r3 = silu_f(w3.w * c0b.y + w3.z * c1b.y + w3.y * c2b.y + w3.x * c3b.y + bb.w);

    uint2 o;
    o.x = packbf(r0, r1);
    o.y = packbf(r2, r3);
    ((uint2*)out16)[idx] = o;
}

// ---------------- chunked selective scan (split kernels, U=4) ---------------
__global__ void scan_p1(const float* __restrict__ delta,
                        const uint32_t* __restrict__ u16,
                        const float* __restrict__ xdbl,
                        const float* __restrict__ A_log,
                        float* __restrict__ gAc, float* __restrict__ gHc) {
    int gt   = blockIdx.x * blockDim.x + threadIdx.x;
    int w    = gt >> 5;
    int lane = gt & 31;
    if (w >= BB * (DI / 2) * GCH) return;

    int pair = w & 1023;
    int b    = (w >> 10) & 1;
    int g    = w >> 11;
    int hi   = lane >> 4;
    int dd   = pair * 2 + hi;
    int n    = lane & 15;
    int t0   = g * CHLEN;

    float Ad = -expf(A_log[dd * DS + n]);
    float h = 0.f, ap = 1.f;

    const size_t base_d = (size_t)(b * LL + t0) * DI + dd;
    const size_t base_u = (size_t)(b * LL + t0) * (DI / 2) + pair;
    const size_t base_x = (size_t)(b * LL + t0) * XDBL_W;

    constexpr int U = 4;
    float de[U], Bn[U];
    uint32_t uup[U];
    #pragma unroll
    for (int j = 0; j < U; j++) {
        de[j]  = delta[base_d + (size_t)j * DI];
        uup[j] = u16 [base_u + (size_t)j * (DI / 2)];
        Bn[j]  = xdbl[base_x + (size_t)j * XDBL_W + DTR + n];
    }
    for (int t = 0; t < CHLEN; t += U) {
        float cde[U], cuu[U], cBn[U];
        #pragma unroll
        for (int j = 0; j < U; j++) {
            cde[j] = de[j]; cBn[j] = Bn[j];
            float2 uv = unpk(uup[j]);
            cuu[j] = hi ? uv.y : uv.x;
        }
        if (t + U < CHLEN) {
            const size_t od = base_d + (size_t)(t + U) * DI;
            const size_t ou = base_u + (size_t)(t + U) * (DI / 2);
            const size_t ox = base_x + (size_t)(t + U) * XDBL_W;
            #pragma unroll
            for (int j = 0; j < U; j++) {
                de[j]  = delta[od + (size_t)j * DI];
                uup[j] = u16 [ou + (size_t)j * (DI / 2)];
                Bn[j]  = xdbl[ox + (size_t)j * XDBL_W + DTR + n];
            }
        }
        #pragma unroll
        for (int j = 0; j < U; j++) {
            float dA = __expf(cde[j] * Ad);
            h = fmaf(dA, h, cde[j] * cuu[j] * cBn[j]);
            ap *= dA;
        }
    }
    size_t idx = ((size_t)(b * DI + dd) * DS + n) * GCH + g;
    gAc[idx] = ap;
    gHc[idx] = h;
}

__global__ void scan_p2(const float* __restrict__ gAc,
                        const float* __restrict__ gHc,
                        float* __restrict__ gCi) {
    int i = blockIdx.x * blockDim.x + threadIdx.x;
    if (i >= BB * DI * DS) return;
    size_t base = (size_t)i * GCH;
    float c = 0.f;
    #pragma unroll
    for (int g = 0; g < GCH; g++) {
        gCi[base + g] = c;
        c = fmaf(gAc[base + g], c, gHc[base + g]);
    }
}

__global__ void scan_p3(const float* __restrict__ delta,
                        const uint32_t* __restrict__ u16,
                        const float* __restrict__ xdbl,
                        const uint32_t* __restrict__ xz16,
                        const float* __restrict__ A_log,
                        const float* __restrict__ Dp,
                        const float* __restrict__ gCi,
                        __nv_bfloat16* __restrict__ y16) {
    int gt   = blockIdx.x * blockDim.x + threadIdx.x;
    int w    = gt >> 5;
    int lane = gt & 31;
    if (w >= BB * (DI / 2) * GCH) return;

    int pair = w & 1023;
    int b    = (w >> 10) & 1;
    int g    = w >> 11;
    int hi   = lane >> 4;
    int dd   = pair * 2 + hi;
    int n    = lane & 15;
    int t0   = g * CHLEN;

    float Ad = -expf(A_log[dd * DS + n]);
    float Dd = Dp[dd];
    float h  = gCi[((size_t)(b * DI + dd) * DS + n) * GCH + g];

    const size_t base_d = (size_t)(b * LL + t0) * DI + dd;
    const size_t base_u = (size_t)(b * LL + t0) * (DI / 2) + pair;
    const size_t base_x = (size_t)(b * LL + t0) * XDBL_W;
    const size_t base_z = (size_t)(b * LL + t0) * (2 * DI / 2) + DI / 2 + pair;

    constexpr int U = 4;
    float de[U], Bn[U], Cn[U];
    uint32_t uup[U], zzp[U];
    #pragma unroll
    for (int j = 0; j < U; j++) {
        de[j]  = delta[base_d + (size_t)j * DI];
        uup[j] = u16 [base_u + (size_t)j * (DI / 2)];
        Bn[j]  = xdbl[base_x + (size_t)j * XDBL_W + DTR + n];
        Cn[j]  = xdbl[base_x + (size_t)j * XDBL_W + DTR + DS + n];
        zzp[j] = xz16[base_z + (size_t)j * (2 * DI / 2)];
    }
    for (int t = 0; t < CHLEN; t += U) {
        float cde[U], cuu[U], cBn[U], cCn[U], czv[U];
        #pragma unroll
        for (int j = 0; j < U; j++) {
            float2 uv = unpk(uup[j]);
            float2 zv = unpk(zzp[j]);
            cde[j] = de[j];
            cuu[j] = hi ? uv.y : uv.x;
            czv[j] = hi ? zv.y : zv.x;
            cBn[j] = Bn[j];
            cCn[j] = Cn[j];
        }
        if (t + U < CHLEN) {
            const size_t od = base_d + (size_t)(t + U) * DI;
            const size_t ou = base_u + (size_t)(t + U) * (DI / 2);
            const size_t ox = base_x + (size_t)(t + U) * XDBL_W;
            const size_t oz = base_z + (size_t)(t + U) * (2 * DI / 2);
            #pragma unroll
            for (int j = 0; j < U; j++) {
                de[j]  = delta[od + (size_t)j * DI];
                uup[j] = u16 [ou + (size_t)j * (DI / 2)];
                Bn[j]  = xdbl[ox + (size_t)j * XDBL_W + DTR + n];
                Cn[j]  = xdbl[ox + (size_t)j * XDBL_W + DTR + DS + n];
                zzp[j] = xz16[oz + (size_t)j * (2 * DI / 2)];
            }
        }
        float yv[U];
        #pragma unroll
        for (int j = 0; j < U; j++) {
            float dA = __expf(cde[j] * Ad);
            h = fmaf(dA, h, cde[j] * cuu[j] * cBn[j]);
            yv[j] = h * cCn[j];
        }
        #pragma unroll
        for (int o = 8; o > 0; o >>= 1) {
            #pragma unroll
            for (int j = 0; j < U; j++)
                yv[j] += __shfl_xor_sync(0xffffffffu, yv[j], o);
        }
        if (n == 0) {
            #pragma unroll
            for (int j = 0; j < U; j++)
                y16[base_d + (size_t)(t + j) * DI] =
                    __float2bfloat16_rn((yv[j] + cuu[j] * Dd) * silu_f(czv[j]));
        }
    }
}

// ---------------- launch ----------------------------------------------------
extern "C" void kernel_launch(void* const* d_in, const int* in_sizes, int n_in,
                              void* d_out, int out_size) {
    const float* x         = (const float*)d_in[0];
    const float* ln_w      = (const float*)d_in[1];
    const float* ln_b      = (const float*)d_in[2];
    const float* in_proj_w = (const float*)d_in[3];
    const float* conv_w    = (const float*)d_in[4];
    const float* conv_b    = (const float*)d_in[5];
    const float* x_proj_w  = (const float*)d_in[6];
    const float* dt_proj_w = (const float*)d_in[7];
    const float* dt_proj_b = (const float*)d_in[8];
    const float* A_log     = (const float*)d_in[9];
    const float* Dp        = (const float*)d_in[10];
    const float* out_pw    = (const float*)d_in[11];
    float* out = (float*)d_out;

    float *xdbl, *delta, *xpart, *Ac, *Hc, *Ci;
    uint32_t *xn16, *xz16, *uconv16, *dt16, *win16, *wx16, *wdt16, *wout16;
    __nv_bfloat16* y16;
    cudaGetSymbolAddress((void**)&xdbl,    g_xdbl);
    cudaGetSymbolAddress((void**)&delta,   g_delta);
    cudaGetSymbolAddress((void**)&xpart,   g_xpart);
    cudaGetSymbolAddress((void**)&xn16,    g_xn16);
    cudaGetSymbolAddress((void**)&xz16,    g_xz16);
    cudaGetSymbolAddress((void**)&uconv16, g_uconv16);
    cudaGetSymbolAddress((void**)&dt16,    g_dt16);
    cudaGetSymbolAddress((void**)&y16,     g_y16);
    cudaGetSymbolAddress((void**)&win16,   g_win16);
    cudaGetSymbolAddress((void**)&wx16,    g_wx16);
    cudaGetSymbolAddress((void**)&wdt16,   g_wdt16);
    cudaGetSymbolAddress((void**)&wout16,  g_wout16);
    cudaGetSymbolAddress((void**)&Ac,      g_Ac);
    cudaGetSymbolAddress((void**)&Hc,      g_Hc);
    cudaGetSymbolAddress((void**)&Ci,      g_Ci);

    // 1. fused LayerNorm + weight conversion (one launch)
    ln_convert_kernel<<<MTOK + CVT_BLOCKS, 256>>>(
        x, ln_w, ln_b, xn16,
        in_proj_w, x_proj_w, dt_proj_w, out_pw, win16, wx16, wdt16, wout16);

    // 2. in_proj -> xz16 (bf16), 64x64 warp tile
    gemm_lm<128, 128, 2, 2, 4><<<dim3((2 * DI) / 128, MTOK / 128), 128>>>(
        xn16, DM / 2, win16, DM / 2, nullptr, 0, DM, nullptr,
        xz16, 2 * DI / 2, 0, 0);

    // 3. conv + SiLU -> uconv16 (4 channels/thread)
    conv_silu_kernel<<<(MTOK * DI / 4 + 255) / 256, 256>>>(
        xz16, conv_w, conv_b, uconv16);

    // 4. x_proj split-K=4 -> partials; reduce -> xdbl fp32 + dt16
    gemm_lm<32, 96, 2, 3, 0><<<dim3(1, MTOK / 32, XKSPLIT), 192>>>(
        uconv16, DI / 2, wx16, DI / 2, xpart, XDBL_W, DI / XKSPLIT, nullptr,
        nullptr, 0, (DI / XKSPLIT) / 2, (size_t)MTOK * XDBL_W);
    xproj_reduce<<<(MTOK * XDBL_W / 2 + 255) / 256, 256>>>(xpart, xdbl, dt16);

    // 5. dt_proj -> delta fp32, 64x64 warp tile
    gemm_lm<128, 128, 2, 2, 1><<<dim3(DI / 128, MTOK / 128), 128>>>(
        dt16, DTR / 2, wdt16, DTR / 2, delta, DI, DTR, dt_proj_b,
        nullptr, 0, 0, 0);

    // 6. chunked selective scan -> y16 (U=4)
    {
        int nw = BB * (DI / 2) * GCH;
        scan_p1<<<(nw * 32) / 256, 256>>>(delta, uconv16, xdbl, A_log, Ac, Hc);
        scan_p2<<<(BB * DI * DS + 255) / 256, 256>>>(Ac, Hc, Ci);
        scan_p3<<<(nw * 32) / 256, 256>>>(delta, uconv16, xdbl, xz16,
                                          A_log, Dp, Ci, y16);
    }

    // 7. out_proj + residual -> out, 64x64 warp tile
    gemm_lm<128, 128, 2, 2, 2><<<dim3(DM / 128, MTOK / 128), 128>>>(
        (const uint32_t*)y16, DI / 2, wout16, DI / 2, out, DM, DI, x,
        nullptr, 0, 0, 0);
}